// round 13
// baseline (speedup 1.0000x reference)
#include <cuda_runtime.h>
#include <math.h>

#define NMAX 100000
#define EMAX 1600000
#define SCAN_T 512
#define SCAN_BLK ((NMAX + SCAN_T - 1) / SCAN_T)   // 196

#define AS_STRIDE 76    // A tile padding (bank-conflict-free frag loads)
#define WS_STRIDE 264   // W tile padding
#define GS_STRIDE 258   // G smem tile stride (float2-aligned)

struct __align__(8) EP { int s; float w; };

// ---------------- scratch (device globals; no allocation at runtime) --------
__device__ unsigned long long g_pack[NMAX];   // (cnt<<44) | fixed20(sum w)
__device__ float g_dinv[NMAX];
__device__ int   g_rank[EMAX];                // edge rank within dst bucket
__device__ int   g_rowptr[NMAX + 1];
__device__ unsigned long long g_scanstate[SCAN_BLK];
__device__ EP    g_ep[EMAX];                // (src, norm) sorted by dst
__device__ float g_A[(size_t)NMAX * 72];    // [AX | AH]
__device__ float g_Wc[72 * 256];            // combined gate weights (tf32)
__device__ float g_bc[256];                 // combined gate bias
__device__ float g_y[(size_t)NMAX * 64];    // cat(relu(LN_o(h)),skip) @ W1
__device__ float g_t[NMAX];                 // scalar per node pre final agg

// ---------------- small helpers ---------------------------------------------
__device__ __forceinline__ float sigmoidf_(float x) { return 1.f / (1.f + __expf(-x)); }
__device__ __forceinline__ float tanh_fast(float x) {
    float y; asm("tanh.approx.f32 %0, %1;" : "=f"(y) : "f"(x)); return y;
}
__device__ __forceinline__ float to_tf32(float x) {
    float r; asm("cvt.rna.tf32.f32 %0, %1;" : "=f"(r) : "f"(x)); return r;
}
__device__ __forceinline__ float warp_sum(float v) {
#pragma unroll
    for (int o = 16; o > 0; o >>= 1) v += __shfl_xor_sync(0xffffffffu, v, o);
    return v;
}
__device__ __forceinline__ void cp_async16(unsigned dst, const void* src) {
    asm volatile("cp.async.cg.shared.global [%0], [%1], 16;"
                 :: "r"(dst), "l"(src) : "memory");
}

// ---------------- fused init: counters + scan-state + weight prep -----------
__global__ void k_init_fused(const float* __restrict__ Wx, const float* __restrict__ Wh,
                             const float* __restrict__ bx, const float* __restrict__ bh,
                             const float* __restrict__ bg, int n, int nbi) {
    int b = blockIdx.x;
    if (b < nbi) {
        int i = b * 256 + threadIdx.x;
        if (i < n) g_pack[i] = 0ull;
    } else if (b < nbi + 72) {
        int k = b - nbi;            // 0..71
        int c = threadIdx.x;        // gate g = c>>6, col j = c&63
        int g = c >> 6, j = c & 63;
        float w = (k < 8) ? Wx[g * 512 + k * 64 + j]
                          : Wh[g * 4096 + (k - 8) * 64 + j];
        g_Wc[k * 256 + c] = to_tf32(w);
        if (k == 0) g_bc[c] = bx[c] + bh[c] + bg[c];
    } else {
        int i = threadIdx.x;
        if (i < SCAN_BLK) g_scanstate[i] = 0ull;
    }
}

// one packed 64-bit atomic per edge; return value gives this edge's rank
__global__ void k_count(const int* __restrict__ dst, const float* __restrict__ w, int E) {
    int e = blockIdx.x * blockDim.x + threadIdx.x;
    if (e < E) {
        unsigned long long fx =
            (unsigned long long)(w[e] * 1048576.0f + 0.5f);   // 2^20 fixed-point
        unsigned long long old = atomicAdd(&g_pack[dst[e]], (1ull << 44) | fx);
        g_rank[e] = (int)(old >> 44);
    }
}

// shfl-based block scan (512 threads = 16 warps)
__device__ __forceinline__ int block_scan_incl(int v, int t, int* wsum) {
    int lane = t & 31, warp = t >> 5;
    int x = v;
#pragma unroll
    for (int off = 1; off < 32; off <<= 1) {
        int y = __shfl_up_sync(0xffffffffu, x, off);
        if (lane >= off) x += y;
    }
    if (lane == 31) wsum[warp] = x;
    __syncthreads();
    if (warp == 0) {
        int s = (lane < 16) ? wsum[lane] : 0;
#pragma unroll
        for (int off = 1; off < 16; off <<= 1) {
            int y = __shfl_up_sync(0xffffffffu, s, off);
            if (lane >= off) s += y;
        }
        if (lane < 16) wsum[lane] = s;
    }
    __syncthreads();
    return x + (warp > 0 ? wsum[warp - 1] : 0);
}

// single-pass scan with decoupled lookback + fused dinv
__global__ void k_scan_fused(int n, int E) {
    __shared__ int wsum[16];
    __shared__ int s_agg;
    __shared__ int s_excl;
    int t = threadIdx.x, b = blockIdx.x;
    int i = b * SCAN_T + t;
    int v = 0;
    if (i < n) {
        unsigned long long pk = g_pack[i];
        v = (int)(pk >> 44);
        float deg = 1.0f + (float)(pk & ((1ull << 44) - 1)) * (1.0f / 1048576.0f);
        g_dinv[i] = rsqrtf(deg);
    }
    int incl = block_scan_incl(v, t, wsum);
    if (t == SCAN_T - 1) s_agg = incl;
    __syncthreads();
    if (t == 0) {
        const unsigned long long F_AGG = 1ull << 62, F_PRE = 2ull << 62;
        if (b == 0) {
            __threadfence();
            atomicExch(&g_scanstate[0], F_PRE | (unsigned int)s_agg);
            s_excl = 0;
        } else {
            __threadfence();
            atomicExch(&g_scanstate[b], F_AGG | (unsigned int)s_agg);
            int excl = 0;
            for (int pb = b - 1; pb >= 0; pb--) {
                unsigned long long s;
                do { s = atomicAdd(&g_scanstate[pb], 0ull); } while ((s >> 62) == 0);
                excl += (int)(s & 0xFFFFFFFFull);
                if ((s >> 62) == 2) break;
            }
            __threadfence();
            atomicExch(&g_scanstate[b], F_PRE | (unsigned int)(excl + s_agg));
            s_excl = excl;
        }
    }
    __syncthreads();
    int excl = s_excl;
    if (i < n) g_rowptr[i] = excl + incl - v;
    if (i == n - 1) g_rowptr[n] = E;
}

// atomic-free scatter using precomputed ranks
__global__ void k_scatter(const int* __restrict__ src, const int* __restrict__ dst,
                          const float* __restrict__ w, int E) {
    int e = blockIdx.x * blockDim.x + threadIdx.x;
    if (e < E) {
        int d = dst[e];
        int s = src[e];
        int pos = g_rowptr[d] + g_rank[e];
        EP p; p.s = s; p.w = g_dinv[d] * w[e] * g_dinv[s];
        g_ep[pos] = p;
    }
}

// ---------------- aggregation 1: A = [agg(X) | agg(H)] ----------------------
// cp.async staged: 16-edge chunks, all row gathers issued async, then smem acc.
__global__ void k_agg1(const float* __restrict__ X, const float* __restrict__ H, int n) {
    __shared__ float sH[8][16][64];   // 32 KB
    __shared__ float sX[8][16][8];    // 4 KB
    int warp = threadIdx.x >> 5, lane = threadIdx.x & 31;
    int node = blockIdx.x * 8 + warp;
    if (node >= n) return;
    int half = lane >> 4, qc = lane & 15;
    float di = g_dinv[node];
    float coef = di * di;             // self loop (w=1)
    const float2* __restrict__ H2 = reinterpret_cast<const float2*>(H);
    float2 hv = H2[(size_t)node * 32 + lane];
    float2 acc = make_float2(coef * hv.x, coef * hv.y);
    float ax = (lane < 8) ? coef * X[node * 8 + lane] : 0.f;

    unsigned shH = (unsigned)__cvta_generic_to_shared(&sH[warp][0][0]);
    unsigned shX = (unsigned)__cvta_generic_to_shared(&sX[warp][0][0]);

    int e0 = g_rowptr[node], e1 = g_rowptr[node + 1];
    for (int base = e0; base < e1; base += 16) {
        int cnt = min(16, e1 - base);
        EP p = g_ep[base + min(lane, cnt - 1)];   // coalesced: all edge metadata
        int ps = p.s; float pw = p.w;
        // issue H row gathers: 2 edges per iteration, lane-chunked 16B
#pragma unroll
        for (int it = 0; it < 8; it++) {
            int j = it * 2 + half;
            int sj = __shfl_sync(0xffffffffu, ps, j);
            if (j < cnt)
                cp_async16(shH + j * 256 + qc * 16,
                           (const char*)H + (size_t)sj * 256 + qc * 16);
        }
        // issue X row gathers: lane -> edge lane>>1, 16B chunk lane&1
        {
            int j = lane >> 1;
            int sj = __shfl_sync(0xffffffffu, ps, j);
            if (j < cnt)
                cp_async16(shX + j * 32 + (lane & 1) * 16,
                           (const char*)X + (size_t)sj * 32 + (lane & 1) * 16);
        }
        asm volatile("cp.async.commit_group;" ::: "memory");
        asm volatile("cp.async.wait_group 0;" ::: "memory");
        __syncwarp();
        // accumulate from smem
#pragma unroll 4
        for (int j = 0; j < cnt; j++) {
            float wj = __shfl_sync(0xffffffffu, pw, j);
            float2 h = *reinterpret_cast<float2*>(&sH[warp][j][lane * 2]);
            acc.x += wj * h.x;
            acc.y += wj * h.y;
            if (lane < 8) ax += wj * sX[warp][j][lane];
        }
        __syncwarp();
    }
    float* Arow = g_A + (size_t)node * 72;
    if (lane < 8) Arow[lane] = ax;
    *reinterpret_cast<float2*>(Arow + 8 + 2 * lane) = acc;
}

// ---------------- fused tc-GEMM + LSTM + LN + head GEMV ----------------------
__global__ void __launch_bounds__(256, 2) k_gemm_lstm_tc(
        const float* __restrict__ C, const float* __restrict__ wc,
        const float* __restrict__ lnhs, const float* __restrict__ lnhb,
        const float* __restrict__ lncs, const float* __restrict__ lncb,
        const float* __restrict__ lnos, const float* __restrict__ lnob,
        const float* __restrict__ skip, const float* __restrict__ W1,
        float* __restrict__ outHidden, float* __restrict__ outCell, int n) {
    extern __shared__ float smem[];
    float* As = smem;                       // 64 x AS_STRIDE   (phase 1)
    float* Ws = smem + 64 * AS_STRIDE;      // 72 x WS_STRIDE   (phase 1)
    float* Gs  = smem;                      // 64 x GS_STRIDE   (phase 2, aliases)
    float* W1s = smem + 64 * GS_STRIDE;     // 66 x 64          (phase 2)

    int nb = blockIdx.x * 64;
    for (int idx = threadIdx.x; idx < 64 * 72; idx += 256) {
        int r = idx / 72, c = idx - r * 72;
        int node = nb + r;
        float v = (node < n) ? g_A[(size_t)node * 72 + c] : 0.f;
        As[r * AS_STRIDE + c] = to_tf32(v);
    }
    for (int idx = threadIdx.x; idx < 72 * 256; idx += 256) {
        int r = idx >> 8, c = idx & 255;
        Ws[r * WS_STRIDE + c] = g_Wc[idx];   // pre-rounded to tf32
    }
    __syncthreads();

    int warp = threadIdx.x >> 5, lane = threadIdx.x & 31;
    int g = lane >> 2, tig = lane & 3;
    int rowblk = (warp & 3) * 16;
    int colhalf = (warp >> 2) * 128;

    float acc[16][4];
#pragma unroll
    for (int t = 0; t < 16; t++)
#pragma unroll
        for (int j = 0; j < 4; j++) acc[t][j] = 0.f;

    const float* Arow0 = As + (rowblk + g) * AS_STRIDE;
    const float* Arow1 = Arow0 + 8 * AS_STRIDE;
#pragma unroll
    for (int ks = 0; ks < 9; ks++) {
        int k0 = ks * 8;
        unsigned a0 = __float_as_uint(Arow0[k0 + tig]);
        unsigned a1 = __float_as_uint(Arow1[k0 + tig]);
        unsigned a2 = __float_as_uint(Arow0[k0 + tig + 4]);
        unsigned a3 = __float_as_uint(Arow1[k0 + tig + 4]);
        const float* Wr0 = Ws + (k0 + tig) * WS_STRIDE + colhalf + g;
        const float* Wr1 = Wr0 + 4 * WS_STRIDE;
#pragma unroll
        for (int t = 0; t < 16; t++) {
            unsigned b0 = __float_as_uint(Wr0[t * 8]);
            unsigned b1 = __float_as_uint(Wr1[t * 8]);
            asm("mma.sync.aligned.m16n8k8.row.col.f32.tf32.tf32.f32 "
                "{%0,%1,%2,%3}, {%4,%5,%6,%7}, {%8,%9}, {%0,%1,%2,%3};"
                : "+f"(acc[t][0]), "+f"(acc[t][1]), "+f"(acc[t][2]), "+f"(acc[t][3])
                : "r"(a0), "r"(a1), "r"(a2), "r"(a3), "r"(b0), "r"(b1));
        }
    }
    __syncthreads();   // all warps done reading As/Ws -> safe to alias as Gs

    // G fragments (+bias) -> smem ; W1 -> smem
#pragma unroll
    for (int t = 0; t < 16; t++) {
        int col = colhalf + t * 8 + tig * 2;
        float2 bias = *reinterpret_cast<const float2*>(g_bc + col);
        *reinterpret_cast<float2*>(Gs + (rowblk + g) * GS_STRIDE + col) =
            make_float2(acc[t][0] + bias.x, acc[t][1] + bias.y);
        *reinterpret_cast<float2*>(Gs + (rowblk + g + 8) * GS_STRIDE + col) =
            make_float2(acc[t][2] + bias.x, acc[t][3] + bias.y);
    }
    for (int i = threadIdx.x; i < 66 * 64; i += 256) W1s[i] = W1[i];
    __syncthreads();

    // ---- LSTM epilogue: warp handles rows warp*8 .. +7 ----
    int j0 = lane, j1 = lane + 32;
    float wci0 = wc[j0],       wci1 = wc[j1];
    float wcf0 = wc[64 + j0],  wcf1 = wc[64 + j1];
    float wco0 = wc[128 + j0], wco1 = wc[128 + j1];
    float hs0 = lnhs[j0], hs1 = lnhs[j1], hb0 = lnhb[j0], hb1 = lnhb[j1];
    float cs0 = lncs[j0], cs1 = lncs[j1], cb0 = lncb[j0], cb1 = lncb[j1];
    float os0 = lnos[j0], os1 = lnos[j1], ob0 = lnob[j0], ob1 = lnob[j1];

    for (int nl = 0; nl < 8; nl++) {
        int r = warp * 8 + nl;
        int node = nb + r;
        if (node >= n) break;
        const float* Grow = Gs + r * GS_STRIDE;
        float g0a = Grow[j0],        g0b = Grow[j1];
        float g1a = Grow[64 + j0],   g1b = Grow[64 + j1];
        float g2a = Grow[128 + j0],  g2b = Grow[128 + j1];
        float g3a = Grow[192 + j0],  g3b = Grow[192 + j1];
        float c0a = C[node * 64 + j0], c0b = C[node * 64 + j1];

        float ia = sigmoidf_(g0a + wci0 * c0a), ib = sigmoidf_(g0b + wci1 * c0b);
        float fa = sigmoidf_(g1a + wcf0 * c0a), fb = sigmoidf_(g1b + wcf1 * c0b);
        float ca = fa * c0a + ia * tanh_fast(g2a);
        float cb = fb * c0b + ib * tanh_fast(g2b);
        float oa = sigmoidf_(g3a + wco0 * ca), ob = sigmoidf_(g3b + wco1 * cb);
        float ha = oa * tanh_fast(ca), hb = ob * tanh_fast(cb);

        float mh = warp_sum(ha + hb) * (1.f / 64.f);
        float dha = ha - mh, dhb = hb - mh;
        float vh = warp_sum(dha * dha + dhb * dhb) * (1.f / 64.f);
        float rh = rsqrtf(vh + 1e-5f);
        outHidden[node * 64 + j0] = dha * rh * hs0 + hb0;
        outHidden[node * 64 + j1] = dhb * rh * hs1 + hb1;

        float mc = warp_sum(ca + cb) * (1.f / 64.f);
        float dca = ca - mc, dcb = cb - mc;
        float vc = warp_sum(dca * dca + dcb * dcb) * (1.f / 64.f);
        float rc = rsqrtf(vc + 1e-5f);
        outCell[node * 64 + j0] = dca * rc * cs0 + cb0;
        outCell[node * 64 + j1] = dcb * rc * cs1 + cb1;

        float r0 = fmaxf(dha * rh * os0 + ob0, 0.f);
        float r1 = fmaxf(dhb * rh * os1 + ob1, 0.f);
        float s0 = skip[node * 2], s1 = skip[node * 2 + 1];
        float y0 = s0 * W1s[64 * 64 + j0] + s1 * W1s[65 * 64 + j0];
        float y1 = s0 * W1s[64 * 64 + j1] + s1 * W1s[65 * 64 + j1];
#pragma unroll
        for (int k = 0; k < 32; k++) {
            float rk = __shfl_sync(0xffffffffu, r0, k);
            y0 += rk * W1s[k * 64 + j0];
            y1 += rk * W1s[k * 64 + j1];
        }
#pragma unroll
        for (int k = 0; k < 32; k++) {
            float rk = __shfl_sync(0xffffffffu, r1, k);
            y0 += rk * W1s[(32 + k) * 64 + j0];
            y1 += rk * W1s[(32 + k) * 64 + j1];
        }
        g_y[(size_t)node * 64 + j0] = y0;
        g_y[(size_t)node * 64 + j1] = y1;
    }
}

// ---------------- agg2 on y (cp.async staged), then t = relu(z+b1) . W2 -----
__global__ void k_agg2(const float* __restrict__ b1, const float* __restrict__ W2, int n) {
    __shared__ float sY[8][16][64];   // 32 KB
    int warp = threadIdx.x >> 5, lane = threadIdx.x & 31;
    int node = blockIdx.x * 8 + warp;
    if (node >= n) return;
    int half = lane >> 4, qc = lane & 15;
    float di = g_dinv[node];
    float coef = di * di;
    const float2* __restrict__ Y2 = reinterpret_cast<const float2*>(g_y);
    float2 yv = Y2[(size_t)node * 32 + lane];
    float2 z = make_float2(coef * yv.x, coef * yv.y);

    unsigned shY = (unsigned)__cvta_generic_to_shared(&sY[warp][0][0]);
    const char* Yb = (const char*)g_y;

    int e0 = g_rowptr[node], e1 = g_rowptr[node + 1];
    for (int base = e0; base < e1; base += 16) {
        int cnt = min(16, e1 - base);
        EP p = g_ep[base + min(lane, cnt - 1)];
        int ps = p.s; float pw = p.w;
#pragma unroll
        for (int it = 0; it < 8; it++) {
            int j = it * 2 + half;
            int sj = __shfl_sync(0xffffffffu, ps, j);
            if (j < cnt)
                cp_async16(shY + j * 256 + qc * 16,
                           Yb + (size_t)sj * 256 + qc * 16);
        }
        asm volatile("cp.async.commit_group;" ::: "memory");
        asm volatile("cp.async.wait_group 0;" ::: "memory");
        __syncwarp();
#pragma unroll 4
        for (int j = 0; j < cnt; j++) {
            float wj = __shfl_sync(0xffffffffu, pw, j);
            float2 y = *reinterpret_cast<float2*>(&sY[warp][j][lane * 2]);
            z.x += wj * y.x;
            z.y += wj * y.y;
        }
        __syncwarp();
    }

    float2 bv = reinterpret_cast<const float2*>(b1)[lane];
    float2 wv = reinterpret_cast<const float2*>(W2)[lane];
    float u = fmaxf(z.x + bv.x, 0.f) * wv.x + fmaxf(z.y + bv.y, 0.f) * wv.y;
    u = warp_sum(u);
    if (lane == 0) g_t[node] = u;
}

// ---------------- agg3 (1-wide) + b2 + residual -> out -----------------------
__global__ void k_agg3(const float* __restrict__ X, const float* __restrict__ b2,
                       float* __restrict__ out, int n) {
    int node = blockIdx.x * blockDim.x + threadIdx.x;
    if (node >= n) return;
    float di = g_dinv[node];
    float s = di * di * g_t[node];
    int e0 = g_rowptr[node], e1 = g_rowptr[node + 1];
    for (int e = e0; e < e1; e++) {
        EP p = g_ep[e];
        s += p.w * g_t[p.s];
    }
    out[node] = s + b2[0] + X[node * 8];
}

// ---------------- launch -----------------------------------------------------
extern "C" void kernel_launch(void* const* d_in, const int* in_sizes, int n_in,
                              void* d_out, int out_size) {
    const float* X    = (const float*)d_in[0];
    const int*   ei   = (const int*)d_in[1];
    const float* ew   = (const float*)d_in[2];
    const float* skip = (const float*)d_in[3];
    const float* H    = (const float*)d_in[4];
    const float* C    = (const float*)d_in[5];
    const float* Wx   = (const float*)d_in[6];
    const float* bx   = (const float*)d_in[7];
    const float* Wh   = (const float*)d_in[8];
    const float* bh   = (const float*)d_in[9];
    const float* wc   = (const float*)d_in[10];
    const float* bg   = (const float*)d_in[11];
    const float* lnhs = (const float*)d_in[12];
    const float* lnhb = (const float*)d_in[13];
    const float* lncs = (const float*)d_in[14];
    const float* lncb = (const float*)d_in[15];
    const float* lnos = (const float*)d_in[16];
    const float* lnob = (const float*)d_in[17];
    const float* W1   = (const float*)d_in[18];
    const float* b1   = (const float*)d_in[19];
    const float* W2   = (const float*)d_in[20];
    const float* b2   = (const float*)d_in[21];

    int n = in_sizes[0] / 8;
    int E = in_sizes[1] / 2;
    if (n > NMAX) n = NMAX;
    if (E > EMAX) E = EMAX;
    const int* src = ei;
    const int* dst = ei + E;

    float* out       = (float*)d_out;
    float* outHidden = out + n;
    float* outCell   = outHidden + (size_t)n * 64;

    int nbi   = (n + 255) / 256;
    int nblkE = (E + 255) / 256;
    int nblkS = (n + SCAN_T - 1) / SCAN_T;
    int nblkW = (n + 7) / 8;
    int nblkN = (n + 255) / 256;

    // 1: init (counters + weights + scan flags)
    k_init_fused<<<nbi + 72 + 1, 256>>>(Wx, Wh, bx, bh, bg, n, nbi);
    // 2: packed degree/count accumulation (records per-edge rank)
    k_count<<<nblkE, 256>>>(dst, ew, E);
    // 3: single-pass scan + dinv
    k_scan_fused<<<nblkS, SCAN_T>>>(n, E);
    // 4: atomic-free CSR scatter
    k_scatter<<<nblkE, 256>>>(src, dst, ew, E);
    // 5: agg1 -> A (cp.async staged gather)
    k_agg1<<<nblkW, 256>>>(X, H, n);
    // 6: fused tc-GEMM + LSTM (G never leaves smem)
    const int FUSED_SMEM = (64 * AS_STRIDE + 72 * WS_STRIDE) * (int)sizeof(float);
    cudaFuncSetAttribute(k_gemm_lstm_tc, cudaFuncAttributeMaxDynamicSharedMemorySize,
                         FUSED_SMEM);
    k_gemm_lstm_tc<<<(n + 63) / 64, 256, FUSED_SMEM>>>(
        C, wc, lnhs, lnhb, lncs, lncb, lnos, lnob, skip, W1,
        outHidden, outCell, n);
    // 7: agg2 (cp.async staged gather) + fc epilogue -> t
    k_agg2<<<nblkW, 256>>>(b1, W2, n);
    // 8: agg3 -> out
    k_agg3<<<nblkN, 256>>>(X, b2, out, n);
}

// round 14
// speedup vs baseline: 1.0137x; 1.0137x over previous
#include <cuda_runtime.h>
#include <math.h>

#define NMAX 100000
#define EMAX 1600000
#define SCAN_T 512
#define SCAN_BLK ((NMAX + SCAN_T - 1) / SCAN_T)   // 196

#define AS_STRIDE 76    // A tile padding (bank-conflict-free frag loads)
#define WS_STRIDE 264   // W tile padding
#define GS_STRIDE 258   // G smem tile stride (float2-aligned)

struct __align__(8) EP { int s; float w; };

// ---------------- scratch (device globals; no allocation at runtime) --------
__device__ unsigned g_pack[NMAX];             // (cnt<<24) | fixed16(sum w); self-cleaned
__device__ float g_dinv[NMAX];
__device__ int   g_rank[EMAX];                // edge rank within dst bucket
__device__ int   g_rowptr[NMAX + 1];
__device__ unsigned long long g_scanstate[SCAN_BLK];
__device__ EP    g_ep[EMAX];                // (src, norm) sorted by dst
__device__ float g_A[(size_t)NMAX * 72];    // [AX | AH]
__device__ float g_Wc[72 * 256];            // combined gate weights (tf32)
__device__ float g_bc[256];                 // combined gate bias
__device__ float g_y[(size_t)NMAX * 64];    // cat(relu(LN_o(h)),skip) @ W1
__device__ float g_t[NMAX];                 // scalar per node pre final agg

// ---------------- small helpers ---------------------------------------------
__device__ __forceinline__ float sigmoidf_(float x) { return 1.f / (1.f + __expf(-x)); }
__device__ __forceinline__ float tanh_fast(float x) {
    float y; asm("tanh.approx.f32 %0, %1;" : "=f"(y) : "f"(x)); return y;
}
__device__ __forceinline__ float to_tf32(float x) {
    float r; asm("cvt.rna.tf32.f32 %0, %1;" : "=f"(r) : "f"(x)); return r;
}
__device__ __forceinline__ float warp_sum(float v) {
#pragma unroll
    for (int o = 16; o > 0; o >>= 1) v += __shfl_xor_sync(0xffffffffu, v, o);
    return v;
}

// ---------------- fused count + scan-state reset + weight prep --------------
// blocks [0,nblkE): one u32 atomic per edge (count+degree+rank)
// block nblkE: reset scan lookback state
// blocks (nblkE, nblkE+72]: gate weight prep (tf32) + combined bias
__global__ void k_count_fused(const int* __restrict__ dst, const float* __restrict__ w,
                              const float* __restrict__ Wx, const float* __restrict__ Wh,
                              const float* __restrict__ bx, const float* __restrict__ bh,
                              const float* __restrict__ bg, int E, int nblkE) {
    int b = blockIdx.x;
    if (b < nblkE) {
        int e = b * 256 + threadIdx.x;
        if (e < E) {
            unsigned fx = (unsigned)(w[e] * 65536.0f + 0.5f);   // 2^16 fixed-point
            unsigned old = atomicAdd(&g_pack[dst[e]], (1u << 24) | fx);
            g_rank[e] = (int)(old >> 24);
        }
    } else if (b == nblkE) {
        int i = threadIdx.x;
        if (i < SCAN_BLK) g_scanstate[i] = 0ull;
    } else {
        int k = b - nblkE - 1;      // 0..71
        int c = threadIdx.x;        // gate g = c>>6, col j = c&63
        int g = c >> 6, j = c & 63;
        float wv = (k < 8) ? Wx[g * 512 + k * 64 + j]
                           : Wh[g * 4096 + (k - 8) * 64 + j];
        g_Wc[k * 256 + c] = to_tf32(wv);
        if (k == 0) g_bc[c] = bx[c] + bh[c] + bg[c];
    }
}

// shfl-based block scan (512 threads = 16 warps)
__device__ __forceinline__ int block_scan_incl(int v, int t, int* wsum) {
    int lane = t & 31, warp = t >> 5;
    int x = v;
#pragma unroll
    for (int off = 1; off < 32; off <<= 1) {
        int y = __shfl_up_sync(0xffffffffu, x, off);
        if (lane >= off) x += y;
    }
    if (lane == 31) wsum[warp] = x;
    __syncthreads();
    if (warp == 0) {
        int s = (lane < 16) ? wsum[lane] : 0;
#pragma unroll
        for (int off = 1; off < 16; off <<= 1) {
            int y = __shfl_up_sync(0xffffffffu, s, off);
            if (lane >= off) s += y;
        }
        if (lane < 16) wsum[lane] = s;
    }
    __syncthreads();
    return x + (warp > 0 ? wsum[warp - 1] : 0);
}

// single-pass scan with decoupled lookback + fused dinv; self-cleans g_pack
__global__ void k_scan_fused(int n, int E) {
    __shared__ int wsum[16];
    __shared__ int s_agg;
    __shared__ int s_excl;
    int t = threadIdx.x, b = blockIdx.x;
    int i = b * SCAN_T + t;
    int v = 0;
    if (i < n) {
        unsigned pk = g_pack[i];
        g_pack[i] = 0u;              // reset for next graph replay
        v = (int)(pk >> 24);
        float deg = 1.0f + (float)(pk & 0xFFFFFFu) * (1.0f / 65536.0f);
        g_dinv[i] = rsqrtf(deg);
    }
    int incl = block_scan_incl(v, t, wsum);
    if (t == SCAN_T - 1) s_agg = incl;
    __syncthreads();
    if (t == 0) {
        const unsigned long long F_AGG = 1ull << 62, F_PRE = 2ull << 62;
        if (b == 0) {
            __threadfence();
            atomicExch(&g_scanstate[0], F_PRE | (unsigned int)s_agg);
            s_excl = 0;
        } else {
            __threadfence();
            atomicExch(&g_scanstate[b], F_AGG | (unsigned int)s_agg);
            int excl = 0;
            for (int pb = b - 1; pb >= 0; pb--) {
                unsigned long long s;
                do { s = atomicAdd(&g_scanstate[pb], 0ull); } while ((s >> 62) == 0);
                excl += (int)(s & 0xFFFFFFFFull);
                if ((s >> 62) == 2) break;
            }
            __threadfence();
            atomicExch(&g_scanstate[b], F_PRE | (unsigned int)(excl + s_agg));
            s_excl = excl;
        }
    }
    __syncthreads();
    int excl = s_excl;
    if (i < n) g_rowptr[i] = excl + incl - v;
    if (i == n - 1) g_rowptr[n] = E;
}

// atomic-free scatter using precomputed ranks
__global__ void k_scatter(const int* __restrict__ src, const int* __restrict__ dst,
                          const float* __restrict__ w, int E) {
    int e = blockIdx.x * blockDim.x + threadIdx.x;
    if (e < E) {
        int d = dst[e];
        int s = src[e];
        int pos = g_rowptr[d] + g_rank[e];
        EP p; p.s = s; p.w = g_dinv[d] * w[e] * g_dinv[s];
        g_ep[pos] = p;
    }
}

// ---------------- aggregation 1: A = [agg(X) | agg(H)] ----------------------
// 2 edges/iteration: lanes 0-15 edge e, lanes 16-31 edge e+1; float4 row loads.
__global__ void k_agg1(const float* __restrict__ X, const float* __restrict__ H, int n) {
    const float4* __restrict__ H4 = reinterpret_cast<const float4*>(H);
    int warp = threadIdx.x >> 5, lane = threadIdx.x & 31;
    int node = blockIdx.x * (blockDim.x >> 5) + warp;
    if (node >= n) return;
    int half = lane >> 4;        // 0 or 1
    int qc = lane & 15;          // float4 column index 0..15
    float di = g_dinv[node];
    float coef = di * di;        // self loop (w=1)

    float4 acc = make_float4(0.f, 0.f, 0.f, 0.f);
    float ax = 0.f;
    if (half == 0) {
        float4 hv = H4[(size_t)node * 16 + qc];
        acc.x = coef * hv.x; acc.y = coef * hv.y;
        acc.z = coef * hv.z; acc.w = coef * hv.w;
        if (qc < 8) ax = coef * X[node * 8 + qc];
    }

    int e0 = g_rowptr[node], e1 = g_rowptr[node + 1];
    int e = e0;
    for (; e + 1 < e1; e += 2) {
        EP p = g_ep[e + half];
        float4 h = H4[(size_t)p.s * 16 + qc];
        acc.x += p.w * h.x; acc.y += p.w * h.y;
        acc.z += p.w * h.z; acc.w += p.w * h.w;
        if (qc < 8) ax += p.w * X[p.s * 8 + qc];
    }
    if (e < e1 && half == 0) {          // odd tail: lower half only
        EP p = g_ep[e];
        float4 h = H4[(size_t)p.s * 16 + qc];
        acc.x += p.w * h.x; acc.y += p.w * h.y;
        acc.z += p.w * h.z; acc.w += p.w * h.w;
        if (qc < 8) ax += p.w * X[p.s * 8 + qc];
    }

    // combine halves (lane l gets l ^ l+16 sum)
    acc.x += __shfl_xor_sync(0xffffffffu, acc.x, 16);
    acc.y += __shfl_xor_sync(0xffffffffu, acc.y, 16);
    acc.z += __shfl_xor_sync(0xffffffffu, acc.z, 16);
    acc.w += __shfl_xor_sync(0xffffffffu, acc.w, 16);
    ax    += __shfl_xor_sync(0xffffffffu, ax, 16);

    if (half == 0) {
        float* Arow = g_A + (size_t)node * 72;
        if (qc < 8) Arow[qc] = ax;
        *reinterpret_cast<float4*>(Arow + 8 + 4 * qc) = acc;
    }
}

// ---------------- fused tc-GEMM + LSTM + LN + head GEMV ----------------------
__global__ void __launch_bounds__(256, 2) k_gemm_lstm_tc(
        const float* __restrict__ C, const float* __restrict__ wc,
        const float* __restrict__ lnhs, const float* __restrict__ lnhb,
        const float* __restrict__ lncs, const float* __restrict__ lncb,
        const float* __restrict__ lnos, const float* __restrict__ lnob,
        const float* __restrict__ skip, const float* __restrict__ W1,
        float* __restrict__ outHidden, float* __restrict__ outCell, int n) {
    extern __shared__ float smem[];
    float* As = smem;                       // 64 x AS_STRIDE   (phase 1)
    float* Ws = smem + 64 * AS_STRIDE;      // 72 x WS_STRIDE   (phase 1)
    float* Gs  = smem;                      // 64 x GS_STRIDE   (phase 2, aliases)
    float* W1s = smem + 64 * GS_STRIDE;     // 66 x 64          (phase 2)

    int nb = blockIdx.x * 64;
    for (int idx = threadIdx.x; idx < 64 * 72; idx += 256) {
        int r = idx / 72, c = idx - r * 72;
        int node = nb + r;
        float v = (node < n) ? g_A[(size_t)node * 72 + c] : 0.f;
        As[r * AS_STRIDE + c] = to_tf32(v);
    }
    for (int idx = threadIdx.x; idx < 72 * 256; idx += 256) {
        int r = idx >> 8, c = idx & 255;
        Ws[r * WS_STRIDE + c] = g_Wc[idx];   // pre-rounded to tf32
    }
    __syncthreads();

    int warp = threadIdx.x >> 5, lane = threadIdx.x & 31;
    int g = lane >> 2, tig = lane & 3;
    int rowblk = (warp & 3) * 16;
    int colhalf = (warp >> 2) * 128;

    float acc[16][4];
#pragma unroll
    for (int t = 0; t < 16; t++)
#pragma unroll
        for (int j = 0; j < 4; j++) acc[t][j] = 0.f;

    const float* Arow0 = As + (rowblk + g) * AS_STRIDE;
    const float* Arow1 = Arow0 + 8 * AS_STRIDE;
#pragma unroll
    for (int ks = 0; ks < 9; ks++) {
        int k0 = ks * 8;
        unsigned a0 = __float_as_uint(Arow0[k0 + tig]);
        unsigned a1 = __float_as_uint(Arow1[k0 + tig]);
        unsigned a2 = __float_as_uint(Arow0[k0 + tig + 4]);
        unsigned a3 = __float_as_uint(Arow1[k0 + tig + 4]);
        const float* Wr0 = Ws + (k0 + tig) * WS_STRIDE + colhalf + g;
        const float* Wr1 = Wr0 + 4 * WS_STRIDE;
#pragma unroll
        for (int t = 0; t < 16; t++) {
            unsigned b0 = __float_as_uint(Wr0[t * 8]);
            unsigned b1 = __float_as_uint(Wr1[t * 8]);
            asm("mma.sync.aligned.m16n8k8.row.col.f32.tf32.tf32.f32 "
                "{%0,%1,%2,%3}, {%4,%5,%6,%7}, {%8,%9}, {%0,%1,%2,%3};"
                : "+f"(acc[t][0]), "+f"(acc[t][1]), "+f"(acc[t][2]), "+f"(acc[t][3])
                : "r"(a0), "r"(a1), "r"(a2), "r"(a3), "r"(b0), "r"(b1));
        }
    }
    __syncthreads();   // all warps done reading As/Ws -> safe to alias as Gs

    // G fragments (+bias) -> smem ; W1 -> smem
#pragma unroll
    for (int t = 0; t < 16; t++) {
        int col = colhalf + t * 8 + tig * 2;
        float2 bias = *reinterpret_cast<const float2*>(g_bc + col);
        *reinterpret_cast<float2*>(Gs + (rowblk + g) * GS_STRIDE + col) =
            make_float2(acc[t][0] + bias.x, acc[t][1] + bias.y);
        *reinterpret_cast<float2*>(Gs + (rowblk + g + 8) * GS_STRIDE + col) =
            make_float2(acc[t][2] + bias.x, acc[t][3] + bias.y);
    }
    for (int i = threadIdx.x; i < 66 * 64; i += 256) W1s[i] = W1[i];
    __syncthreads();

    // ---- LSTM epilogue: warp handles rows warp*8 .. +7 ----
    int j0 = lane, j1 = lane + 32;
    float wci0 = wc[j0],       wci1 = wc[j1];
    float wcf0 = wc[64 + j0],  wcf1 = wc[64 + j1];
    float wco0 = wc[128 + j0], wco1 = wc[128 + j1];
    float hs0 = lnhs[j0], hs1 = lnhs[j1], hb0 = lnhb[j0], hb1 = lnhb[j1];
    float cs0 = lncs[j0], cs1 = lncs[j1], cb0 = lncb[j0], cb1 = lncb[j1];
    float os0 = lnos[j0], os1 = lnos[j1], ob0 = lnob[j0], ob1 = lnob[j1];

    for (int nl = 0; nl < 8; nl++) {
        int r = warp * 8 + nl;
        int node = nb + r;
        if (node >= n) break;
        const float* Grow = Gs + r * GS_STRIDE;
        float g0a = Grow[j0],        g0b = Grow[j1];
        float g1a = Grow[64 + j0],   g1b = Grow[64 + j1];
        float g2a = Grow[128 + j0],  g2b = Grow[128 + j1];
        float g3a = Grow[192 + j0],  g3b = Grow[192 + j1];
        float c0a = C[node * 64 + j0], c0b = C[node * 64 + j1];

        float ia = sigmoidf_(g0a + wci0 * c0a), ib = sigmoidf_(g0b + wci1 * c0b);
        float fa = sigmoidf_(g1a + wcf0 * c0a), fb = sigmoidf_(g1b + wcf1 * c0b);
        float ca = fa * c0a + ia * tanh_fast(g2a);
        float cb = fb * c0b + ib * tanh_fast(g2b);
        float oa = sigmoidf_(g3a + wco0 * ca), ob = sigmoidf_(g3b + wco1 * cb);
        float ha = oa * tanh_fast(ca), hb = ob * tanh_fast(cb);

        float mh = warp_sum(ha + hb) * (1.f / 64.f);
        float dha = ha - mh, dhb = hb - mh;
        float vh = warp_sum(dha * dha + dhb * dhb) * (1.f / 64.f);
        float rh = rsqrtf(vh + 1e-5f);
        outHidden[node * 64 + j0] = dha * rh * hs0 + hb0;
        outHidden[node * 64 + j1] = dhb * rh * hs1 + hb1;

        float mc = warp_sum(ca + cb) * (1.f / 64.f);
        float dca = ca - mc, dcb = cb - mc;
        float vc = warp_sum(dca * dca + dcb * dcb) * (1.f / 64.f);
        float rc = rsqrtf(vc + 1e-5f);
        outCell[node * 64 + j0] = dca * rc * cs0 + cb0;
        outCell[node * 64 + j1] = dcb * rc * cs1 + cb1;

        float r0 = fmaxf(dha * rh * os0 + ob0, 0.f);
        float r1 = fmaxf(dhb * rh * os1 + ob1, 0.f);
        float s0 = skip[node * 2], s1 = skip[node * 2 + 1];
        float y0 = s0 * W1s[64 * 64 + j0] + s1 * W1s[65 * 64 + j0];
        float y1 = s0 * W1s[64 * 64 + j1] + s1 * W1s[65 * 64 + j1];
#pragma unroll
        for (int k = 0; k < 32; k++) {
            float rk = __shfl_sync(0xffffffffu, r0, k);
            y0 += rk * W1s[k * 64 + j0];
            y1 += rk * W1s[k * 64 + j1];
        }
#pragma unroll
        for (int k = 0; k < 32; k++) {
            float rk = __shfl_sync(0xffffffffu, r1, k);
            y0 += rk * W1s[(32 + k) * 64 + j0];
            y1 += rk * W1s[(32 + k) * 64 + j1];
        }
        g_y[(size_t)node * 64 + j0] = y0;
        g_y[(size_t)node * 64 + j1] = y1;
    }
}

// ---------------- agg2 on y, then t = relu(z+b1) . W2 -----------------------
// 2 edges/iteration, float4 lane loads (same scheme as agg1).
__global__ void k_agg2(const float* __restrict__ b1, const float* __restrict__ W2, int n) {
    const float4* __restrict__ Y4 = reinterpret_cast<const float4*>(g_y);
    int warp = threadIdx.x >> 5, lane = threadIdx.x & 31;
    int node = blockIdx.x * (blockDim.x >> 5) + warp;
    if (node >= n) return;
    int half = lane >> 4;
    int qc = lane & 15;
    float di = g_dinv[node];
    float coef = di * di;

    float4 z = make_float4(0.f, 0.f, 0.f, 0.f);
    if (half == 0) {
        float4 yv = Y4[(size_t)node * 16 + qc];
        z.x = coef * yv.x; z.y = coef * yv.y;
        z.z = coef * yv.z; z.w = coef * yv.w;
    }

    int e0 = g_rowptr[node], e1 = g_rowptr[node + 1];
    int e = e0;
    for (; e + 1 < e1; e += 2) {
        EP p = g_ep[e + half];
        float4 y = Y4[(size_t)p.s * 16 + qc];
        z.x += p.w * y.x; z.y += p.w * y.y;
        z.z += p.w * y.z; z.w += p.w * y.w;
    }
    if (e < e1 && half == 0) {
        EP p = g_ep[e];
        float4 y = Y4[(size_t)p.s * 16 + qc];
        z.x += p.w * y.x; z.y += p.w * y.y;
        z.z += p.w * y.z; z.w += p.w * y.w;
    }

    z.x += __shfl_xor_sync(0xffffffffu, z.x, 16);
    z.y += __shfl_xor_sync(0xffffffffu, z.y, 16);
    z.z += __shfl_xor_sync(0xffffffffu, z.z, 16);
    z.w += __shfl_xor_sync(0xffffffffu, z.w, 16);

    // epilogue: both halves hold identical z -> reduce over 16 lanes
    float4 bv = reinterpret_cast<const float4*>(b1)[qc];
    float4 wv = reinterpret_cast<const float4*>(W2)[qc];
    float u = fmaxf(z.x + bv.x, 0.f) * wv.x + fmaxf(z.y + bv.y, 0.f) * wv.y
            + fmaxf(z.z + bv.z, 0.f) * wv.z + fmaxf(z.w + bv.w, 0.f) * wv.w;
#pragma unroll
    for (int o = 8; o > 0; o >>= 1) u += __shfl_xor_sync(0xffffffffu, u, o);
    if (lane == 0) g_t[node] = u;
}

// ---------------- agg3 (1-wide) + b2 + residual -> out -----------------------
__global__ void k_agg3(const float* __restrict__ X, const float* __restrict__ b2,
                       float* __restrict__ out, int n) {
    int node = blockIdx.x * blockDim.x + threadIdx.x;
    if (node >= n) return;
    float di = g_dinv[node];
    float s = di * di * g_t[node];
    int e0 = g_rowptr[node], e1 = g_rowptr[node + 1];
    for (int e = e0; e < e1; e++) {
        EP p = g_ep[e];
        s += p.w * g_t[p.s];
    }
    out[node] = s + b2[0] + X[node * 8];
}

// ---------------- launch -----------------------------------------------------
extern "C" void kernel_launch(void* const* d_in, const int* in_sizes, int n_in,
                              void* d_out, int out_size) {
    const float* X    = (const float*)d_in[0];
    const int*   ei   = (const int*)d_in[1];
    const float* ew   = (const float*)d_in[2];
    const float* skip = (const float*)d_in[3];
    const float* H    = (const float*)d_in[4];
    const float* C    = (const float*)d_in[5];
    const float* Wx   = (const float*)d_in[6];
    const float* bx   = (const float*)d_in[7];
    const float* Wh   = (const float*)d_in[8];
    const float* bh   = (const float*)d_in[9];
    const float* wc   = (const float*)d_in[10];
    const float* bg   = (const float*)d_in[11];
    const float* lnhs = (const float*)d_in[12];
    const float* lnhb = (const float*)d_in[13];
    const float* lncs = (const float*)d_in[14];
    const float* lncb = (const float*)d_in[15];
    const float* lnos = (const float*)d_in[16];
    const float* lnob = (const float*)d_in[17];
    const float* W1   = (const float*)d_in[18];
    const float* b1   = (const float*)d_in[19];
    const float* W2   = (const float*)d_in[20];
    const float* b2   = (const float*)d_in[21];

    int n = in_sizes[0] / 8;
    int E = in_sizes[1] / 2;
    if (n > NMAX) n = NMAX;
    if (E > EMAX) E = EMAX;
    const int* src = ei;
    const int* dst = ei + E;

    float* out       = (float*)d_out;
    float* outHidden = out + n;
    float* outCell   = outHidden + (size_t)n * 64;

    int nblkE = (E + 255) / 256;
    int nblkS = (n + SCAN_T - 1) / SCAN_T;
    int nblkW = (n + 7) / 8;
    int nblkN = (n + 255) / 256;

    // 1: fused count (u32 packed atomic, per-edge rank) + scan-state reset + weights
    k_count_fused<<<nblkE + 1 + 72, 256>>>(dst, ew, Wx, Wh, bx, bh, bg, E, nblkE);
    // 2: single-pass scan + dinv (self-cleans g_pack for next replay)
    k_scan_fused<<<nblkS, SCAN_T>>>(n, E);
    // 3: atomic-free CSR scatter
    k_scatter<<<nblkE, 256>>>(src, dst, ew, E);
    // 4: agg1 -> A (2-edge float4 gather)
    k_agg1<<<nblkW, 256>>>(X, H, n);
    // 5: fused tc-GEMM + LSTM (G never leaves smem)
    const int FUSED_SMEM = (64 * AS_STRIDE + 72 * WS_STRIDE) * (int)sizeof(float);
    cudaFuncSetAttribute(k_gemm_lstm_tc, cudaFuncAttributeMaxDynamicSharedMemorySize,
                         FUSED_SMEM);
    k_gemm_lstm_tc<<<(n + 63) / 64, 256, FUSED_SMEM>>>(
        C, wc, lnhs, lnhb, lncs, lncb, lnos, lnob, skip, W1,
        outHidden, outCell, n);
    // 6: agg2 (2-edge float4 gather) + fc epilogue -> t
    k_agg2<<<nblkW, 256>>>(b1, W2, n);
    // 7: agg3 -> out
    k_agg3<<<nblkN, 256>>>(X, b2, out, n);
}

// round 15
// speedup vs baseline: 1.1833x; 1.1673x over previous
#include <cuda_runtime.h>
#include <math.h>

#define NMAX 100000
#define NPAD 100032     // NMAX rounded up to 64 (GEMM tile overrun safety)
#define EMAX 1600000
#define SCAN_T 512
#define SCAN_BLK ((NMAX + SCAN_T - 1) / SCAN_T)   // 196

#define AS_STRIDE 76    // A/R tile stride (bank-conflict-free frag loads)
#define WS_STRIDE 264   // W tile stride
#define GS_STRIDE 258   // G smem tile stride (float2-aligned)
#define W1S_STRIDE 72   // W1 B-tile stride (72%32=8 -> conflict-free)

// smem layout (floats):
//  [0, 4864)        As (phase1) / Rs (phase2/3)   64 x 76
//  [4864, 23872)    Ws (phase1)                   72 x 264
//  [4864, 21376)    Gs (phase2, aliases Ws)       64 x 258
//  [21376, 26560)   W1s (phase2/3)                72 x 72
#define SM_WS   4864
#define SM_W1S  21376
#define SM_FLOATS 26560

struct __align__(8) EP { int s; float w; };

// ---------------- scratch (device globals; no allocation at runtime) --------
__device__ unsigned g_pack[NMAX];             // (cnt<<24) | fixed16(sum w); self-cleaned
__device__ float g_dinv[NMAX];
__device__ int   g_rank[EMAX];                // edge rank within dst bucket
__device__ int   g_rowptr[NMAX + 1];
__device__ unsigned long long g_scanstate[SCAN_BLK];
__device__ EP    g_ep[EMAX];                   // (src, norm) sorted by dst
__device__ float g_A[(size_t)NPAD * 76];       // [AX | AH] tf32, GEMM layout
__device__ float g_Wc[72 * 256];               // combined gate weights (tf32)
__device__ float g_bc[256];                    // combined gate bias
__device__ float g_y[(size_t)NMAX * 64];       // cat(relu(LN_o(h)),skip) @ W1
__device__ float g_t[NMAX];                    // scalar per node pre final agg

// ---------------- small helpers ---------------------------------------------
__device__ __forceinline__ float sigmoidf_(float x) { return 1.f / (1.f + __expf(-x)); }
__device__ __forceinline__ float tanh_fast(float x) {
    float y; asm("tanh.approx.f32 %0, %1;" : "=f"(y) : "f"(x)); return y;
}
__device__ __forceinline__ float to_tf32(float x) {
    float r; asm("cvt.rna.tf32.f32 %0, %1;" : "=f"(r) : "f"(x)); return r;
}
__device__ __forceinline__ float warp_sum(float v) {
#pragma unroll
    for (int o = 16; o > 0; o >>= 1) v += __shfl_xor_sync(0xffffffffu, v, o);
    return v;
}
#define MMA_TF32(acc, a0, a1, a2, a3, b0, b1) \
    asm("mma.sync.aligned.m16n8k8.row.col.f32.tf32.tf32.f32 " \
        "{%0,%1,%2,%3}, {%4,%5,%6,%7}, {%8,%9}, {%0,%1,%2,%3};" \
        : "+f"((acc)[0]), "+f"((acc)[1]), "+f"((acc)[2]), "+f"((acc)[3]) \
        : "r"(a0), "r"(a1), "r"(a2), "r"(a3), "r"(b0), "r"(b1))

// ---------------- fused count + scan-state reset + weight prep --------------
__global__ void k_count_fused(const int* __restrict__ dst, const float* __restrict__ w,
                              const float* __restrict__ Wx, const float* __restrict__ Wh,
                              const float* __restrict__ bx, const float* __restrict__ bh,
                              const float* __restrict__ bg, int E, int nblkE) {
    int b = blockIdx.x;
    if (b < nblkE) {
        int e = b * 256 + threadIdx.x;
        if (e < E) {
            unsigned fx = (unsigned)(w[e] * 65536.0f + 0.5f);   // 2^16 fixed-point
            unsigned old = atomicAdd(&g_pack[dst[e]], (1u << 24) | fx);
            g_rank[e] = (int)(old >> 24);
        }
    } else if (b == nblkE) {
        int i = threadIdx.x;
        if (i < SCAN_BLK) g_scanstate[i] = 0ull;
    } else {
        int k = b - nblkE - 1;      // 0..71
        int c = threadIdx.x;        // gate g = c>>6, col j = c&63
        int g = c >> 6, j = c & 63;
        float wv = (k < 8) ? Wx[g * 512 + k * 64 + j]
                           : Wh[g * 4096 + (k - 8) * 64 + j];
        g_Wc[k * 256 + c] = to_tf32(wv);
        if (k == 0) g_bc[c] = bx[c] + bh[c] + bg[c];
    }
}

// shfl-based block scan (512 threads = 16 warps)
__device__ __forceinline__ int block_scan_incl(int v, int t, int* wsum) {
    int lane = t & 31, warp = t >> 5;
    int x = v;
#pragma unroll
    for (int off = 1; off < 32; off <<= 1) {
        int y = __shfl_up_sync(0xffffffffu, x, off);
        if (lane >= off) x += y;
    }
    if (lane == 31) wsum[warp] = x;
    __syncthreads();
    if (warp == 0) {
        int s = (lane < 16) ? wsum[lane] : 0;
#pragma unroll
        for (int off = 1; off < 16; off <<= 1) {
            int y = __shfl_up_sync(0xffffffffu, s, off);
            if (lane >= off) s += y;
        }
        if (lane < 16) wsum[lane] = s;
    }
    __syncthreads();
    return x + (warp > 0 ? wsum[warp - 1] : 0);
}

// single-pass scan with decoupled lookback + fused dinv; self-cleans g_pack
__global__ void k_scan_fused(int n, int E) {
    __shared__ int wsum[16];
    __shared__ int s_agg;
    __shared__ int s_excl;
    int t = threadIdx.x, b = blockIdx.x;
    int i = b * SCAN_T + t;
    int v = 0;
    if (i < n) {
        unsigned pk = g_pack[i];
        g_pack[i] = 0u;              // reset for next graph replay
        v = (int)(pk >> 24);
        float deg = 1.0f + (float)(pk & 0xFFFFFFu) * (1.0f / 65536.0f);
        g_dinv[i] = rsqrtf(deg);
    }
    int incl = block_scan_incl(v, t, wsum);
    if (t == SCAN_T - 1) s_agg = incl;
    __syncthreads();
    if (t == 0) {
        const unsigned long long F_AGG = 1ull << 62, F_PRE = 2ull << 62;
        if (b == 0) {
            __threadfence();
            atomicExch(&g_scanstate[0], F_PRE | (unsigned int)s_agg);
            s_excl = 0;
        } else {
            __threadfence();
            atomicExch(&g_scanstate[b], F_AGG | (unsigned int)s_agg);
            int excl = 0;
            for (int pb = b - 1; pb >= 0; pb--) {
                unsigned long long s;
                do { s = atomicAdd(&g_scanstate[pb], 0ull); } while ((s >> 62) == 0);
                excl += (int)(s & 0xFFFFFFFFull);
                if ((s >> 62) == 2) break;
            }
            __threadfence();
            atomicExch(&g_scanstate[b], F_PRE | (unsigned int)(excl + s_agg));
            s_excl = excl;
        }
    }
    __syncthreads();
    int excl = s_excl;
    if (i < n) g_rowptr[i] = excl + incl - v;
    if (i == n - 1) g_rowptr[n] = E;
}

// atomic-free scatter using precomputed ranks
__global__ void k_scatter(const int* __restrict__ src, const int* __restrict__ dst,
                          const float* __restrict__ w, int E) {
    int e = blockIdx.x * blockDim.x + threadIdx.x;
    if (e < E) {
        int d = dst[e];
        int s = src[e];
        int pos = g_rowptr[d] + g_rank[e];
        EP p; p.s = s; p.w = g_dinv[d] * w[e] * g_dinv[s];
        g_ep[pos] = p;
    }
}

// ---------------- aggregation 1: A = [agg(X) | agg(H)] ----------------------
// 2 edges/iteration; writes tf32 values in GEMM layout (stride 76).
__global__ void k_agg1(const float* __restrict__ X, const float* __restrict__ H, int n) {
    const float4* __restrict__ H4 = reinterpret_cast<const float4*>(H);
    int warp = threadIdx.x >> 5, lane = threadIdx.x & 31;
    int node = blockIdx.x * (blockDim.x >> 5) + warp;
    if (node >= n) return;
    int half = lane >> 4;        // 0 or 1
    int qc = lane & 15;          // float4 column index 0..15
    float di = g_dinv[node];
    float coef = di * di;        // self loop (w=1)

    float4 acc = make_float4(0.f, 0.f, 0.f, 0.f);
    float ax = 0.f;
    if (half == 0) {
        float4 hv = H4[(size_t)node * 16 + qc];
        acc.x = coef * hv.x; acc.y = coef * hv.y;
        acc.z = coef * hv.z; acc.w = coef * hv.w;
        if (qc < 8) ax = coef * X[node * 8 + qc];
    }

    int e0 = g_rowptr[node], e1 = g_rowptr[node + 1];
    int e = e0;
    for (; e + 1 < e1; e += 2) {
        EP p = g_ep[e + half];
        float4 h = H4[(size_t)p.s * 16 + qc];
        acc.x += p.w * h.x; acc.y += p.w * h.y;
        acc.z += p.w * h.z; acc.w += p.w * h.w;
        if (qc < 8) ax += p.w * X[p.s * 8 + qc];
    }
    if (e < e1 && half == 0) {          // odd tail: lower half only
        EP p = g_ep[e];
        float4 h = H4[(size_t)p.s * 16 + qc];
        acc.x += p.w * h.x; acc.y += p.w * h.y;
        acc.z += p.w * h.z; acc.w += p.w * h.w;
        if (qc < 8) ax += p.w * X[p.s * 8 + qc];
    }

    // combine halves
    acc.x += __shfl_xor_sync(0xffffffffu, acc.x, 16);
    acc.y += __shfl_xor_sync(0xffffffffu, acc.y, 16);
    acc.z += __shfl_xor_sync(0xffffffffu, acc.z, 16);
    acc.w += __shfl_xor_sync(0xffffffffu, acc.w, 16);
    ax    += __shfl_xor_sync(0xffffffffu, ax, 16);

    if (half == 0) {
        float* Arow = g_A + (size_t)node * AS_STRIDE;
        if (qc < 8) Arow[qc] = to_tf32(ax);
        float4 t4 = make_float4(to_tf32(acc.x), to_tf32(acc.y),
                                to_tf32(acc.z), to_tf32(acc.w));
        *reinterpret_cast<float4*>(Arow + 8 + 4 * qc) = t4;
    }
}

// ---------------- fused tc-GEMM + LSTM + LN + tc head-GEMM -------------------
// Phase 1: G = A @ Wc + bias (tf32 mma) -> Gs (smem)
// Phase 2: LSTM gates + 2 LNs; r, skip -> Rs (tf32, smem); W1 -> W1s (tf32)
// Phase 3: y = Rs @ W1s (tf32 mma) -> g_y
__global__ void __launch_bounds__(256, 2) k_gemm_lstm_tc(
        const float* __restrict__ C, const float* __restrict__ wc,
        const float* __restrict__ lnhs, const float* __restrict__ lnhb,
        const float* __restrict__ lncs, const float* __restrict__ lncb,
        const float* __restrict__ lnos, const float* __restrict__ lnob,
        const float* __restrict__ skip, const float* __restrict__ W1,
        float* __restrict__ outHidden, float* __restrict__ outCell, int n) {
    extern __shared__ float smem[];
    float* As  = smem;              // 64 x 76 (phase 1)
    float* Rs  = smem;              // 64 x 76 (phase 2/3, aliases As)
    float* Ws  = smem + SM_WS;      // 72 x 264 (phase 1)
    float* Gs  = smem + SM_WS;      // 64 x 258 (phase 2, aliases Ws)
    float* W1s = smem + SM_W1S;     // 72 x 72 (phase 2/3)

    int nb = blockIdx.x * 64;
    // A tile: linear float4 copy (pre-tf32, GEMM layout in gmem)
    {
        const float4* Asrc = reinterpret_cast<const float4*>(g_A + (size_t)nb * AS_STRIDE);
        float4* Adst = reinterpret_cast<float4*>(As);
        for (int idx = threadIdx.x; idx < 64 * (AS_STRIDE / 4); idx += 256)
            Adst[idx] = Asrc[idx];
    }
    // W tile: float4 loads into padded stride
    for (int idx = threadIdx.x; idx < 72 * 64; idx += 256) {
        int r = idx >> 6, c4 = idx & 63;
        *reinterpret_cast<float4*>(Ws + r * WS_STRIDE + c4 * 4) =
            reinterpret_cast<const float4*>(g_Wc)[idx];
    }
    __syncthreads();

    int warp = threadIdx.x >> 5, lane = threadIdx.x & 31;
    int g = lane >> 2, tig = lane & 3;
    int rowblk = (warp & 3) * 16;
    int colhalf = (warp >> 2) * 128;

    float acc[16][4];
#pragma unroll
    for (int t = 0; t < 16; t++)
#pragma unroll
        for (int j = 0; j < 4; j++) acc[t][j] = 0.f;

    const float* Arow0 = As + (rowblk + g) * AS_STRIDE;
    const float* Arow1 = Arow0 + 8 * AS_STRIDE;
#pragma unroll
    for (int ks = 0; ks < 9; ks++) {
        int k0 = ks * 8;
        unsigned a0 = __float_as_uint(Arow0[k0 + tig]);
        unsigned a1 = __float_as_uint(Arow1[k0 + tig]);
        unsigned a2 = __float_as_uint(Arow0[k0 + tig + 4]);
        unsigned a3 = __float_as_uint(Arow1[k0 + tig + 4]);
        const float* Wr0 = Ws + (k0 + tig) * WS_STRIDE + colhalf + g;
        const float* Wr1 = Wr0 + 4 * WS_STRIDE;
#pragma unroll
        for (int t = 0; t < 16; t++) {
            unsigned b0 = __float_as_uint(Wr0[t * 8]);
            unsigned b1 = __float_as_uint(Wr1[t * 8]);
            MMA_TF32(acc[t], a0, a1, a2, a3, b0, b1);
        }
    }
    __syncthreads();   // As/Ws dead -> Gs/Rs/W1s live

    // G fragments (+bias) -> Gs ; W1 -> W1s (tf32, zero-padded rows 66..71);
    // zero Rs pad cols 66..71
#pragma unroll
    for (int t = 0; t < 16; t++) {
        int col = colhalf + t * 8 + tig * 2;
        float2 bias = *reinterpret_cast<const float2*>(g_bc + col);
        *reinterpret_cast<float2*>(Gs + (rowblk + g) * GS_STRIDE + col) =
            make_float2(acc[t][0] + bias.x, acc[t][1] + bias.y);
        *reinterpret_cast<float2*>(Gs + (rowblk + g + 8) * GS_STRIDE + col) =
            make_float2(acc[t][2] + bias.x, acc[t][3] + bias.y);
    }
    for (int idx = threadIdx.x; idx < 72 * 64; idx += 256) {
        int k = idx >> 6, j = idx & 63;
        W1s[k * W1S_STRIDE + j] = (k < 66) ? to_tf32(W1[idx]) : 0.f;
    }
    for (int idx = threadIdx.x; idx < 64 * 6; idx += 256) {
        int r = idx / 6, c = 66 + idx - r * 6;
        Rs[r * AS_STRIDE + c] = 0.f;
    }
    __syncthreads();

    // ---- Phase 2: LSTM + LNs; warp handles rows warp*8 .. +7 ----
    int j0 = lane, j1 = lane + 32;
    float wci0 = wc[j0],       wci1 = wc[j1];
    float wcf0 = wc[64 + j0],  wcf1 = wc[64 + j1];
    float wco0 = wc[128 + j0], wco1 = wc[128 + j1];
    float hs0 = lnhs[j0], hs1 = lnhs[j1], hb0 = lnhb[j0], hb1 = lnhb[j1];
    float cs0 = lncs[j0], cs1 = lncs[j1], cb0 = lncb[j0], cb1 = lncb[j1];
    float os0 = lnos[j0], os1 = lnos[j1], ob0 = lnob[j0], ob1 = lnob[j1];

    for (int nl = 0; nl < 8; nl++) {
        int r = warp * 8 + nl;
        int node = nb + r;
        if (node >= n) break;
        const float* Grow = Gs + r * GS_STRIDE;
        float g0a = Grow[j0],        g0b = Grow[j1];
        float g1a = Grow[64 + j0],   g1b = Grow[64 + j1];
        float g2a = Grow[128 + j0],  g2b = Grow[128 + j1];
        float g3a = Grow[192 + j0],  g3b = Grow[192 + j1];
        float c0a = C[node * 64 + j0], c0b = C[node * 64 + j1];

        float ia = sigmoidf_(g0a + wci0 * c0a), ib = sigmoidf_(g0b + wci1 * c0b);
        float fa = sigmoidf_(g1a + wcf0 * c0a), fb = sigmoidf_(g1b + wcf1 * c0b);
        float ca = fa * c0a + ia * tanh_fast(g2a);
        float cb = fb * c0b + ib * tanh_fast(g2b);
        float oa = sigmoidf_(g3a + wco0 * ca), ob = sigmoidf_(g3b + wco1 * cb);
        float ha = oa * tanh_fast(ca), hb = ob * tanh_fast(cb);

        float mh = warp_sum(ha + hb) * (1.f / 64.f);
        float dha = ha - mh, dhb = hb - mh;
        float vh = warp_sum(dha * dha + dhb * dhb) * (1.f / 64.f);
        float rh = rsqrtf(vh + 1e-5f);
        outHidden[node * 64 + j0] = dha * rh * hs0 + hb0;
        outHidden[node * 64 + j1] = dhb * rh * hs1 + hb1;

        float mc = warp_sum(ca + cb) * (1.f / 64.f);
        float dca = ca - mc, dcb = cb - mc;
        float vc = warp_sum(dca * dca + dcb * dcb) * (1.f / 64.f);
        float rc = rsqrtf(vc + 1e-5f);
        outCell[node * 64 + j0] = dca * rc * cs0 + cb0;
        outCell[node * 64 + j1] = dcb * rc * cs1 + cb1;

        float r0 = fmaxf(dha * rh * os0 + ob0, 0.f);
        float r1 = fmaxf(dhb * rh * os1 + ob1, 0.f);
        float* Rrow = Rs + r * AS_STRIDE;
        Rrow[j0] = to_tf32(r0);
        Rrow[j1] = to_tf32(r1);
        if (lane == 0) {
            Rrow[64] = to_tf32(skip[node * 2]);
            Rrow[65] = to_tf32(skip[node * 2 + 1]);
        }
    }
    __syncthreads();

    // ---- Phase 3: y = cat(r, skip) @ W1 on tensor cores ----
    {
        int colh2 = (warp >> 2) * 32;
        float acc2[4][4];
#pragma unroll
        for (int t = 0; t < 4; t++)
#pragma unroll
            for (int j = 0; j < 4; j++) acc2[t][j] = 0.f;

        const float* Rrow0 = Rs + (rowblk + g) * AS_STRIDE;
        const float* Rrow1 = Rrow0 + 8 * AS_STRIDE;
#pragma unroll
        for (int ks = 0; ks < 9; ks++) {
            int k0 = ks * 8;
            unsigned a0 = __float_as_uint(Rrow0[k0 + tig]);
            unsigned a1 = __float_as_uint(Rrow1[k0 + tig]);
            unsigned a2 = __float_as_uint(Rrow0[k0 + tig + 4]);
            unsigned a3 = __float_as_uint(Rrow1[k0 + tig + 4]);
            const float* Wr0 = W1s + (k0 + tig) * W1S_STRIDE + colh2 + g;
            const float* Wr1 = Wr0 + 4 * W1S_STRIDE;
#pragma unroll
            for (int t = 0; t < 4; t++) {
                unsigned b0 = __float_as_uint(Wr0[t * 8]);
                unsigned b1 = __float_as_uint(Wr1[t * 8]);
                MMA_TF32(acc2[t], a0, a1, a2, a3, b0, b1);
            }
        }
        int row0 = nb + rowblk + g, row1 = row0 + 8;
#pragma unroll
        for (int t = 0; t < 4; t++) {
            int col = colh2 + t * 8 + tig * 2;
            if (row0 < n)
                *reinterpret_cast<float2*>(g_y + (size_t)row0 * 64 + col) =
                    make_float2(acc2[t][0], acc2[t][1]);
            if (row1 < n)
                *reinterpret_cast<float2*>(g_y + (size_t)row1 * 64 + col) =
                    make_float2(acc2[t][2], acc2[t][3]);
        }
    }
}

// ---------------- agg2 on y, then t = relu(z+b1) . W2 -----------------------
__global__ void k_agg2(const float* __restrict__ b1, const float* __restrict__ W2, int n) {
    const float4* __restrict__ Y4 = reinterpret_cast<const float4*>(g_y);
    int warp = threadIdx.x >> 5, lane = threadIdx.x & 31;
    int node = blockIdx.x * (blockDim.x >> 5) + warp;
    if (node >= n) return;
    int half = lane >> 4;
    int qc = lane & 15;
    float di = g_dinv[node];
    float coef = di * di;

    float4 z = make_float4(0.f, 0.f, 0.f, 0.f);
    if (half == 0) {
        float4 yv = Y4[(size_t)node * 16 + qc];
        z.x = coef * yv.x; z.y = coef * yv.y;
        z.z = coef * yv.z; z.w = coef * yv.w;
    }

    int e0 = g_rowptr[node], e1 = g_rowptr[node + 1];
    int e = e0;
    for (; e + 1 < e1; e += 2) {
        EP p = g_ep[e + half];
        float4 y = Y4[(size_t)p.s * 16 + qc];
        z.x += p.w * y.x; z.y += p.w * y.y;
        z.z += p.w * y.z; z.w += p.w * y.w;
    }
    if (e < e1 && half == 0) {
        EP p = g_ep[e];
        float4 y = Y4[(size_t)p.s * 16 + qc];
        z.x += p.w * y.x; z.y += p.w * y.y;
        z.z += p.w * y.z; z.w += p.w * y.w;
    }

    z.x += __shfl_xor_sync(0xffffffffu, z.x, 16);
    z.y += __shfl_xor_sync(0xffffffffu, z.y, 16);
    z.z += __shfl_xor_sync(0xffffffffu, z.z, 16);
    z.w += __shfl_xor_sync(0xffffffffu, z.w, 16);

    float4 bv = reinterpret_cast<const float4*>(b1)[qc];
    float4 wv = reinterpret_cast<const float4*>(W2)[qc];
    float u = fmaxf(z.x + bv.x, 0.f) * wv.x + fmaxf(z.y + bv.y, 0.f) * wv.y
            + fmaxf(z.z + bv.z, 0.f) * wv.z + fmaxf(z.w + bv.w, 0.f) * wv.w;
#pragma unroll
    for (int o = 8; o > 0; o >>= 1) u += __shfl_xor_sync(0xffffffffu, u, o);
    if (lane == 0) g_t[node] = u;
}

// ---------------- agg3 (1-wide) + b2 + residual -> out -----------------------
__global__ void k_agg3(const float* __restrict__ X, const float* __restrict__ b2,
                       float* __restrict__ out, int n) {
    int node = blockIdx.x * blockDim.x + threadIdx.x;
    if (node >= n) return;
    float di = g_dinv[node];
    float s = di * di * g_t[node];
    int e0 = g_rowptr[node], e1 = g_rowptr[node + 1];
    for (int e = e0; e < e1; e++) {
        EP p = g_ep[e];
        s += p.w * g_t[p.s];
    }
    out[node] = s + b2[0] + X[node * 8];
}

// ---------------- launch -----------------------------------------------------
extern "C" void kernel_launch(void* const* d_in, const int* in_sizes, int n_in,
                              void* d_out, int out_size) {
    const float* X    = (const float*)d_in[0];
    const int*   ei   = (const int*)d_in[1];
    const float* ew   = (const float*)d_in[2];
    const float* skip = (const float*)d_in[3];
    const float* H    = (const float*)d_in[4];
    const float* C    = (const float*)d_in[5];
    const float* Wx   = (const float*)d_in[6];
    const float* bx   = (const float*)d_in[7];
    const float* Wh   = (const float*)d_in[8];
    const float* bh   = (const float*)d_in[9];
    const float* wc   = (const float*)d_in[10];
    const float* bg   = (const float*)d_in[11];
    const float* lnhs = (const float*)d_in[12];
    const float* lnhb = (const float*)d_in[13];
    const float* lncs = (const float*)d_in[14];
    const float* lncb = (const float*)d_in[15];
    const float* lnos = (const float*)d_in[16];
    const float* lnob = (const float*)d_in[17];
    const float* W1   = (const float*)d_in[18];
    const float* b1   = (const float*)d_in[19];
    const float* W2   = (const float*)d_in[20];
    const float* b2   = (const float*)d_in[21];

    int n = in_sizes[0] / 8;
    int E = in_sizes[1] / 2;
    if (n > NMAX) n = NMAX;
    if (E > EMAX) E = EMAX;
    const int* src = ei;
    const int* dst = ei + E;

    float* out       = (float*)d_out;
    float* outHidden = out + n;
    float* outCell   = outHidden + (size_t)n * 64;

    int nblkE = (E + 255) / 256;
    int nblkS = (n + SCAN_T - 1) / SCAN_T;
    int nblkW = (n + 7) / 8;
    int nblkN = (n + 255) / 256;

    // 1: fused count (u32 packed atomic, per-edge rank) + scan-state reset + weights
    k_count_fused<<<nblkE + 1 + 72, 256>>>(dst, ew, Wx, Wh, bx, bh, bg, E, nblkE);
    // 2: single-pass scan + dinv (self-cleans g_pack for next replay)
    k_scan_fused<<<nblkS, SCAN_T>>>(n, E);
    // 3: atomic-free CSR scatter
    k_scatter<<<nblkE, 256>>>(src, dst, ew, E);
    // 4: agg1 -> A (2-edge float4 gather; tf32 GEMM layout output)
    k_agg1<<<nblkW, 256>>>(X, H, n);
    // 5: fused tc-GEMM + LSTM + tc head-GEMM
    const int FUSED_SMEM = SM_FLOATS * (int)sizeof(float);
    cudaFuncSetAttribute(k_gemm_lstm_tc, cudaFuncAttributeMaxDynamicSharedMemorySize,
                         FUSED_SMEM);
    k_gemm_lstm_tc<<<(n + 63) / 64, 256, FUSED_SMEM>>>(
        C, wc, lnhs, lnhb, lncs, lncb, lnos, lnob, skip, W1,
        outHidden, outCell, n);
    // 6: agg2 (2-edge float4 gather) + fc epilogue -> t
    k_agg2<<<nblkW, 256>>>(b1, W2, n);
    // 7: agg3 -> out
    k_agg3<<<nblkN, 256>>>(X, b2, out, n);
}

// round 16
// speedup vs baseline: 1.2882x; 1.0886x over previous
#include <cuda_runtime.h>
#include <math.h>

#define NMAX 100000
#define NPAD 100032     // NMAX rounded up to 64 (GEMM tile overrun safety)
#define EMAX 1600000
#define SCAN_T 512
#define SCAN_BLK ((NMAX + SCAN_T - 1) / SCAN_T)   // 196

#define AS_STRIDE 76    // A/R tile stride (bank-conflict-free frag loads)
#define WS_STRIDE 264   // W tile stride
#define GS_STRIDE 258   // G smem tile stride (float2-aligned)
#define W1S_STRIDE 72   // W1 B-tile stride

#define SM_WS   4864
#define SM_W1S  21376
#define SM_FLOATS 26560

struct __align__(8) EP { int s; float w; };

// ---------------- scratch (device globals; no allocation at runtime) --------
__device__ unsigned g_pack[NMAX];             // (cnt<<24) | fixed16(sum w); self-cleaned
__device__ float g_dinv[NMAX];
__device__ int   g_rank[EMAX];                // edge rank within dst bucket
__device__ int   g_rowptr[NMAX + 1];
__device__ unsigned long long g_scanstate[SCAN_BLK];
__device__ EP    g_ep[EMAX];                   // (src, norm) sorted by dst
__device__ float g_A[(size_t)NPAD * 76];       // [AX | AH] tf32, GEMM layout
__device__ float g_Wc[72 * 256];               // combined gate weights (tf32)
__device__ float g_bc[256];                    // combined gate bias
__device__ float g_y[(size_t)NMAX * 64];       // cat(relu(LN_o(h)),skip) @ W1
__device__ float g_t[NMAX];                    // scalar per node pre final agg

// ---------------- small helpers ---------------------------------------------
__device__ __forceinline__ float sigmoidf_(float x) { return 1.f / (1.f + __expf(-x)); }
__device__ __forceinline__ float tanh_fast(float x) {
    float y; asm("tanh.approx.f32 %0, %1;" : "=f"(y) : "f"(x)); return y;
}
__device__ __forceinline__ float to_tf32(float x) {
    float r; asm("cvt.rna.tf32.f32 %0, %1;" : "=f"(r) : "f"(x)); return r;
}
#define MMA_TF32(acc, a0, a1, a2, a3, b0, b1) \
    asm("mma.sync.aligned.m16n8k8.row.col.f32.tf32.tf32.f32 " \
        "{%0,%1,%2,%3}, {%4,%5,%6,%7}, {%8,%9}, {%0,%1,%2,%3};" \
        : "+f"((acc)[0]), "+f"((acc)[1]), "+f"((acc)[2]), "+f"((acc)[3]) \
        : "r"(a0), "r"(a1), "r"(a2), "r"(a3), "r"(b0), "r"(b1))

// ---------------- fused count + scan-state reset + weight prep --------------
__global__ void k_count_fused(const int* __restrict__ dst, const float* __restrict__ w,
                              const float* __restrict__ Wx, const float* __restrict__ Wh,
                              const float* __restrict__ bx, const float* __restrict__ bh,
                              const float* __restrict__ bg, int E, int nblkE) {
    int b = blockIdx.x;
    if (b < nblkE) {
        int e = b * 256 + threadIdx.x;
        if (e < E) {
            unsigned fx = (unsigned)(w[e] * 65536.0f + 0.5f);   // 2^16 fixed-point
            unsigned old = atomicAdd(&g_pack[dst[e]], (1u << 24) | fx);
            g_rank[e] = (int)(old >> 24);
        }
    } else if (b == nblkE) {
        int i = threadIdx.x;
        if (i < SCAN_BLK) g_scanstate[i] = 0ull;
    } else {
        int k = b - nblkE - 1;      // 0..71
        int c = threadIdx.x;        // gate g = c>>6, col j = c&63
        int g = c >> 6, j = c & 63;
        float wv = (k < 8) ? Wx[g * 512 + k * 64 + j]
                           : Wh[g * 4096 + (k - 8) * 64 + j];
        g_Wc[k * 256 + c] = to_tf32(wv);
        if (k == 0) g_bc[c] = bx[c] + bh[c] + bg[c];
    }
}

// shfl-based block scan (512 threads = 16 warps)
__device__ __forceinline__ int block_scan_incl(int v, int t, int* wsum) {
    int lane = t & 31, warp = t >> 5;
    int x = v;
#pragma unroll
    for (int off = 1; off < 32; off <<= 1) {
        int y = __shfl_up_sync(0xffffffffu, x, off);
        if (lane >= off) x += y;
    }
    if (lane == 31) wsum[warp] = x;
    __syncthreads();
    if (warp == 0) {
        int s = (lane < 16) ? wsum[lane] : 0;
#pragma unroll
        for (int off = 1; off < 16; off <<= 1) {
            int y = __shfl_up_sync(0xffffffffu, s, off);
            if (lane >= off) s += y;
        }
        if (lane < 16) wsum[lane] = s;
    }
    __syncthreads();
    return x + (warp > 0 ? wsum[warp - 1] : 0);
}

// single-pass scan with decoupled lookback + fused dinv; self-cleans g_pack
__global__ void k_scan_fused(int n, int E) {
    __shared__ int wsum[16];
    __shared__ int s_agg;
    __shared__ int s_excl;
    int t = threadIdx.x, b = blockIdx.x;
    int i = b * SCAN_T + t;
    int v = 0;
    if (i < n) {
        unsigned pk = g_pack[i];
        g_pack[i] = 0u;              // reset for next graph replay
        v = (int)(pk >> 24);
        float deg = 1.0f + (float)(pk & 0xFFFFFFu) * (1.0f / 65536.0f);
        g_dinv[i] = rsqrtf(deg);
    }
    int incl = block_scan_incl(v, t, wsum);
    if (t == SCAN_T - 1) s_agg = incl;
    __syncthreads();
    if (t == 0) {
        const unsigned long long F_AGG = 1ull << 62, F_PRE = 2ull << 62;
        if (b == 0) {
            __threadfence();
            atomicExch(&g_scanstate[0], F_PRE | (unsigned int)s_agg);
            s_excl = 0;
        } else {
            __threadfence();
            atomicExch(&g_scanstate[b], F_AGG | (unsigned int)s_agg);
            int excl = 0;
            for (int pb = b - 1; pb >= 0; pb--) {
                unsigned long long s;
                do { s = atomicAdd(&g_scanstate[pb], 0ull); } while ((s >> 62) == 0);
                excl += (int)(s & 0xFFFFFFFFull);
                if ((s >> 62) == 2) break;
            }
            __threadfence();
            atomicExch(&g_scanstate[b], F_PRE | (unsigned int)(excl + s_agg));
            s_excl = excl;
        }
    }
    __syncthreads();
    int excl = s_excl;
    if (i < n) g_rowptr[i] = excl + incl - v;
    if (i == n - 1) g_rowptr[n] = E;
}

// atomic-free scatter using precomputed ranks
__global__ void k_scatter(const int* __restrict__ src, const int* __restrict__ dst,
                          const float* __restrict__ w, int E) {
    int e = blockIdx.x * blockDim.x + threadIdx.x;
    if (e < E) {
        int d = dst[e];
        int s = src[e];
        int pos = g_rowptr[d] + g_rank[e];
        EP p; p.s = s; p.w = g_dinv[d] * w[e] * g_dinv[s];
        g_ep[pos] = p;
    }
}

// ---------------- aggregation 1: A = [agg(X) | agg(H)] ----------------------
// 2 edges/iteration; writes tf32 values in GEMM layout (stride 76).
__global__ void k_agg1(const float* __restrict__ X, const float* __restrict__ H, int n) {
    const float4* __restrict__ H4 = reinterpret_cast<const float4*>(H);
    int warp = threadIdx.x >> 5, lane = threadIdx.x & 31;
    int node = blockIdx.x * (blockDim.x >> 5) + warp;
    if (node >= n) return;
    int half = lane >> 4;        // 0 or 1
    int qc = lane & 15;          // float4 column index 0..15
    float di = g_dinv[node];
    float coef = di * di;        // self loop (w=1)

    float4 acc = make_float4(0.f, 0.f, 0.f, 0.f);
    float ax = 0.f;
    if (half == 0) {
        float4 hv = H4[(size_t)node * 16 + qc];
        acc.x = coef * hv.x; acc.y = coef * hv.y;
        acc.z = coef * hv.z; acc.w = coef * hv.w;
        if (qc < 8) ax = coef * X[node * 8 + qc];
    }

    int e0 = g_rowptr[node], e1 = g_rowptr[node + 1];
    int e = e0;
    for (; e + 1 < e1; e += 2) {
        EP p = g_ep[e + half];
        float4 h = H4[(size_t)p.s * 16 + qc];
        acc.x += p.w * h.x; acc.y += p.w * h.y;
        acc.z += p.w * h.z; acc.w += p.w * h.w;
        if (qc < 8) ax += p.w * X[p.s * 8 + qc];
    }
    if (e < e1 && half == 0) {          // odd tail: lower half only
        EP p = g_ep[e];
        float4 h = H4[(size_t)p.s * 16 + qc];
        acc.x += p.w * h.x; acc.y += p.w * h.y;
        acc.z += p.w * h.z; acc.w += p.w * h.w;
        if (qc < 8) ax += p.w * X[p.s * 8 + qc];
    }

    // combine halves
    acc.x += __shfl_xor_sync(0xffffffffu, acc.x, 16);
    acc.y += __shfl_xor_sync(0xffffffffu, acc.y, 16);
    acc.z += __shfl_xor_sync(0xffffffffu, acc.z, 16);
    acc.w += __shfl_xor_sync(0xffffffffu, acc.w, 16);
    ax    += __shfl_xor_sync(0xffffffffu, ax, 16);

    if (half == 0) {
        float* Arow = g_A + (size_t)node * AS_STRIDE;
        if (qc < 8) Arow[qc] = to_tf32(ax);
        float4 t4 = make_float4(to_tf32(acc.x), to_tf32(acc.y),
                                to_tf32(acc.z), to_tf32(acc.w));
        *reinterpret_cast<float4*>(Arow + 8 + 4 * qc) = t4;
    }
}

// ---------------- fused tc-GEMM + LSTM + LN + tc head-GEMM -------------------
__global__ void __launch_bounds__(256, 2) k_gemm_lstm_tc(
        const float* __restrict__ C, const float* __restrict__ wc,
        const float* __restrict__ lnhs, const float* __restrict__ lnhb,
        const float* __restrict__ lncs, const float* __restrict__ lncb,
        const float* __restrict__ lnos, const float* __restrict__ lnob,
        const float* __restrict__ skip, const float* __restrict__ W1,
        float* __restrict__ outHidden, float* __restrict__ outCell, int n) {
    extern __shared__ float smem[];
    float* As  = smem;              // 64 x 76 (phase 1)
    float* Rs  = smem;              // 64 x 76 (phase 2/3, aliases As)
    float* Ws  = smem + SM_WS;      // 72 x 264 (phase 1)
    float* Gs  = smem + SM_WS;      // 64 x 258 (phase 2, aliases Ws)
    float* W1s = smem + SM_W1S;     // 72 x 72 (phase 2/3)

    int nb = blockIdx.x * 64;
    {
        const float4* Asrc = reinterpret_cast<const float4*>(g_A + (size_t)nb * AS_STRIDE);
        float4* Adst = reinterpret_cast<float4*>(As);
        for (int idx = threadIdx.x; idx < 64 * (AS_STRIDE / 4); idx += 256)
            Adst[idx] = Asrc[idx];
    }
    for (int idx = threadIdx.x; idx < 72 * 64; idx += 256) {
        int r = idx >> 6, c4 = idx & 63;
        *reinterpret_cast<float4*>(Ws + r * WS_STRIDE + c4 * 4) =
            reinterpret_cast<const float4*>(g_Wc)[idx];
    }
    __syncthreads();

    int warp = threadIdx.x >> 5, lane = threadIdx.x & 31;
    int g = lane >> 2, tig = lane & 3;
    int rowblk = (warp & 3) * 16;
    int colhalf = (warp >> 2) * 128;

    float acc[16][4];
#pragma unroll
    for (int t = 0; t < 16; t++)
#pragma unroll
        for (int j = 0; j < 4; j++) acc[t][j] = 0.f;

    const float* Arow0 = As + (rowblk + g) * AS_STRIDE;
    const float* Arow1 = Arow0 + 8 * AS_STRIDE;
#pragma unroll
    for (int ks = 0; ks < 9; ks++) {
        int k0 = ks * 8;
        unsigned a0 = __float_as_uint(Arow0[k0 + tig]);
        unsigned a1 = __float_as_uint(Arow1[k0 + tig]);
        unsigned a2 = __float_as_uint(Arow0[k0 + tig + 4]);
        unsigned a3 = __float_as_uint(Arow1[k0 + tig + 4]);
        const float* Wr0 = Ws + (k0 + tig) * WS_STRIDE + colhalf + g;
        const float* Wr1 = Wr0 + 4 * WS_STRIDE;
#pragma unroll
        for (int t = 0; t < 16; t++) {
            unsigned b0 = __float_as_uint(Wr0[t * 8]);
            unsigned b1 = __float_as_uint(Wr1[t * 8]);
            MMA_TF32(acc[t], a0, a1, a2, a3, b0, b1);
        }
    }
    __syncthreads();   // As/Ws dead -> Gs/Rs/W1s live

    // G fragments (+bias) -> Gs ; W1 -> W1s ; zero Rs pad cols
#pragma unroll
    for (int t = 0; t < 16; t++) {
        int col = colhalf + t * 8 + tig * 2;
        float2 bias = *reinterpret_cast<const float2*>(g_bc + col);
        *reinterpret_cast<float2*>(Gs + (rowblk + g) * GS_STRIDE + col) =
            make_float2(acc[t][0] + bias.x, acc[t][1] + bias.y);
        *reinterpret_cast<float2*>(Gs + (rowblk + g + 8) * GS_STRIDE + col) =
            make_float2(acc[t][2] + bias.x, acc[t][3] + bias.y);
    }
    for (int idx = threadIdx.x; idx < 72 * 64; idx += 256) {
        int k = idx >> 6, j = idx & 63;
        W1s[k * W1S_STRIDE + j] = (k < 66) ? to_tf32(W1[idx]) : 0.f;
    }
    for (int idx = threadIdx.x; idx < 64 * 6; idx += 256) {
        int r = idx / 6, c = 66 + idx - r * 6;
        Rs[r * AS_STRIDE + c] = 0.f;
    }

    // ---- C prefetch for all 8 nodes (acc registers now dead; MLP=16) ----
    int j0 = lane, j1 = lane + 32;
    float c0a[8], c0b[8];
#pragma unroll
    for (int nl = 0; nl < 8; nl++) {
        int node = nb + warp * 8 + nl;
        if (node >= n) node = n - 1;
        c0a[nl] = C[node * 64 + j0];
        c0b[nl] = C[node * 64 + j1];
    }
    __syncthreads();

    // ---- Phase 2: LSTM + LNs; warp handles rows warp*8 .. +7 ----
    float wci0 = wc[j0],       wci1 = wc[j1];
    float wcf0 = wc[64 + j0],  wcf1 = wc[64 + j1];
    float wco0 = wc[128 + j0], wco1 = wc[128 + j1];
    float hs0 = lnhs[j0], hs1 = lnhs[j1], hb0 = lnhb[j0], hb1 = lnhb[j1];
    float cs0 = lncs[j0], cs1 = lncs[j1], cb0 = lncb[j0], cb1 = lncb[j1];
    float os0 = lnos[j0], os1 = lnos[j1], ob0 = lnob[j0], ob1 = lnob[j1];

#pragma unroll
    for (int nl = 0; nl < 8; nl++) {
        int r = warp * 8 + nl;
        int node = nb + r;
        if (node >= n) break;
        const float* Grow = Gs + r * GS_STRIDE;
        float g0a = Grow[j0],        g0b = Grow[j1];
        float g1a = Grow[64 + j0],   g1b = Grow[64 + j1];
        float g2a = Grow[128 + j0],  g2b = Grow[128 + j1];
        float g3a = Grow[192 + j0],  g3b = Grow[192 + j1];

        float ia = sigmoidf_(g0a + wci0 * c0a[nl]), ib = sigmoidf_(g0b + wci1 * c0b[nl]);
        float fa = sigmoidf_(g1a + wcf0 * c0a[nl]), fb = sigmoidf_(g1b + wcf1 * c0b[nl]);
        float ca = fa * c0a[nl] + ia * tanh_fast(g2a);
        float cb = fb * c0b[nl] + ib * tanh_fast(g2b);
        float oa = sigmoidf_(g3a + wco0 * ca), ob = sigmoidf_(g3b + wco1 * cb);
        float ha = oa * tanh_fast(ca), hb = ob * tanh_fast(cb);

        // 4 independent reductions: sum/sumsq for h and c (ILP-interleaved)
        float sh = ha + hb, qh = ha * ha + hb * hb;
        float sc = ca + cb, qcv = ca * ca + cb * cb;
#pragma unroll
        for (int o = 16; o > 0; o >>= 1) {
            sh  += __shfl_xor_sync(0xffffffffu, sh, o);
            qh  += __shfl_xor_sync(0xffffffffu, qh, o);
            sc  += __shfl_xor_sync(0xffffffffu, sc, o);
            qcv += __shfl_xor_sync(0xffffffffu, qcv, o);
        }
        float mh = sh * (1.f / 64.f);
        float vh = qh * (1.f / 64.f) - mh * mh;
        float rh = rsqrtf(vh + 1e-5f);
        float mc = sc * (1.f / 64.f);
        float vc = qcv * (1.f / 64.f) - mc * mc;
        float rc = rsqrtf(vc + 1e-5f);

        float dha = ha - mh, dhb = hb - mh;
        float dca = ca - mc, dcb = cb - mc;
        outHidden[node * 64 + j0] = dha * rh * hs0 + hb0;
        outHidden[node * 64 + j1] = dhb * rh * hs1 + hb1;
        outCell[node * 64 + j0] = dca * rc * cs0 + cb0;
        outCell[node * 64 + j1] = dcb * rc * cs1 + cb1;

        float r0 = fmaxf(dha * rh * os0 + ob0, 0.f);
        float r1 = fmaxf(dhb * rh * os1 + ob1, 0.f);
        float* Rrow = Rs + r * AS_STRIDE;
        Rrow[j0] = to_tf32(r0);
        Rrow[j1] = to_tf32(r1);
        if (lane == 0) {
            Rrow[64] = to_tf32(skip[node * 2]);
            Rrow[65] = to_tf32(skip[node * 2 + 1]);
        }
    }
    __syncthreads();

    // ---- Phase 3: y = cat(r, skip) @ W1 on tensor cores ----
    {
        int colh2 = (warp >> 2) * 32;
        float acc2[4][4];
#pragma unroll
        for (int t = 0; t < 4; t++)
#pragma unroll
            for (int j = 0; j < 4; j++) acc2[t][j] = 0.f;

        const float* Rrow0 = Rs + (rowblk + g) * AS_STRIDE;
        const float* Rrow1 = Rrow0 + 8 * AS_STRIDE;
#pragma unroll
        for (int ks = 0; ks < 9; ks++) {
            int k0 = ks * 8;
            unsigned a0 = __float_as_uint(Rrow0[k0 + tig]);
            unsigned a1 = __float_as_uint(Rrow1[k0 + tig]);
            unsigned a2 = __float_as_uint(Rrow0[k0 + tig + 4]);
            unsigned a3 = __float_as_uint(Rrow1[k0 + tig + 4]);
            const float* Wr0 = W1s + (k0 + tig) * W1S_STRIDE + colh2 + g;
            const float* Wr1 = Wr0 + 4 * W1S_STRIDE;
#pragma unroll
            for (int t = 0; t < 4; t++) {
                unsigned b0 = __float_as_uint(Wr0[t * 8]);
                unsigned b1 = __float_as_uint(Wr1[t * 8]);
                MMA_TF32(acc2[t], a0, a1, a2, a3, b0, b1);
            }
        }
        int row0 = nb + rowblk + g, row1 = row0 + 8;
#pragma unroll
        for (int t = 0; t < 4; t++) {
            int col = colh2 + t * 8 + tig * 2;
            if (row0 < n)
                *reinterpret_cast<float2*>(g_y + (size_t)row0 * 64 + col) =
                    make_float2(acc2[t][0], acc2[t][1]);
            if (row1 < n)
                *reinterpret_cast<float2*>(g_y + (size_t)row1 * 64 + col) =
                    make_float2(acc2[t][2], acc2[t][3]);
        }
    }
}

// ---------------- agg2 on y, then t = relu(z+b1) . W2 -----------------------
__global__ void k_agg2(const float* __restrict__ b1, const float* __restrict__ W2, int n) {
    const float4* __restrict__ Y4 = reinterpret_cast<const float4*>(g_y);
    int warp = threadIdx.x >> 5, lane = threadIdx.x & 31;
    int node = blockIdx.x * (blockDim.x >> 5) + warp;
    if (node >= n) return;
    int half = lane >> 4;
    int qc = lane & 15;
    float di = g_dinv[node];
    float coef = di * di;

    float4 z = make_float4(0.f, 0.f, 0.f, 0.f);
    if (half == 0) {
        float4 yv = Y4[(size_t)node * 16 + qc];
        z.x = coef * yv.x; z.y = coef * yv.y;
        z.z = coef * yv.z; z.w = coef * yv.w;
    }

    int e0 = g_rowptr[node], e1 = g_rowptr[node + 1];
    int e = e0;
    for (; e + 1 < e1; e += 2) {
        EP p = g_ep[e + half];
        float4 y = Y4[(size_t)p.s * 16 + qc];
        z.x += p.w * y.x; z.y += p.w * y.y;
        z.z += p.w * y.z; z.w += p.w * y.w;
    }
    if (e < e1 && half == 0) {
        EP p = g_ep[e];
        float4 y = Y4[(size_t)p.s * 16 + qc];
        z.x += p.w * y.x; z.y += p.w * y.y;
        z.z += p.w * y.z; z.w += p.w * y.w;
    }

    z.x += __shfl_xor_sync(0xffffffffu, z.x, 16);
    z.y += __shfl_xor_sync(0xffffffffu, z.y, 16);
    z.z += __shfl_xor_sync(0xffffffffu, z.z, 16);
    z.w += __shfl_xor_sync(0xffffffffu, z.w, 16);

    float4 bv = reinterpret_cast<const float4*>(b1)[qc];
    float4 wv = reinterpret_cast<const float4*>(W2)[qc];
    float u = fmaxf(z.x + bv.x, 0.f) * wv.x + fmaxf(z.y + bv.y, 0.f) * wv.y
            + fmaxf(z.z + bv.z, 0.f) * wv.z + fmaxf(z.w + bv.w, 0.f) * wv.w;
#pragma unroll
    for (int o = 8; o > 0; o >>= 1) u += __shfl_xor_sync(0xffffffffu, u, o);
    if (lane == 0) g_t[node] = u;
}

// ---------------- agg3 (1-wide) + b2 + residual -> out -----------------------
__global__ void k_agg3(const float* __restrict__ X, const float* __restrict__ b2,
                       float* __restrict__ out, int n) {
    int node = blockIdx.x * blockDim.x + threadIdx.x;
    if (node >= n) return;
    float di = g_dinv[node];
    float s = di * di * g_t[node];
    int e0 = g_rowptr[node], e1 = g_rowptr[node + 1];
    for (int e = e0; e < e1; e++) {
        EP p = g_ep[e];
        s += p.w * g_t[p.s];
    }
    out[node] = s + b2[0] + X[node * 8];
}

// ---------------- launch -----------------------------------------------------
extern "C" void kernel_launch(void* const* d_in, const int* in_sizes, int n_in,
                              void* d_out, int out_size) {
    const float* X    = (const float*)d_in[0];
    const int*   ei   = (const int*)d_in[1];
    const float* ew   = (const float*)d_in[2];
    const float* skip = (const float*)d_in[3];
    const float* H    = (const float*)d_in[4];
    const float* C    = (const float*)d_in[5];
    const float* Wx   = (const float*)d_in[6];
    const float* bx   = (const float*)d_in[7];
    const float* Wh   = (const float*)d_in[8];
    const float* bh   = (const float*)d_in[9];
    const float* wc   = (const float*)d_in[10];
    const float* bg   = (const float*)d_in[11];
    const float* lnhs = (const float*)d_in[12];
    const float* lnhb = (const float*)d_in[13];
    const float* lncs = (const float*)d_in[14];
    const float* lncb = (const float*)d_in[15];
    const float* lnos = (const float*)d_in[16];
    const float* lnob = (const float*)d_in[17];
    const float* W1   = (const float*)d_in[18];
    const float* b1   = (const float*)d_in[19];
    const float* W2   = (const float*)d_in[20];
    const float* b2   = (const float*)d_in[21];

    int n = in_sizes[0] / 8;
    int E = in_sizes[1] / 2;
    if (n > NMAX) n = NMAX;
    if (E > EMAX) E = EMAX;
    const int* src = ei;
    const int* dst = ei + E;

    float* out       = (float*)d_out;
    float* outHidden = out + n;
    float* outCell   = outHidden + (size_t)n * 64;

    int nblkE = (E + 255) / 256;
    int nblkS = (n + SCAN_T - 1) / SCAN_T;
    int nblkW = (n + 7) / 8;
    int nblkN = (n + 255) / 256;

    // 1: fused count (u32 packed atomic, per-edge rank) + scan-state reset + weights
    k_count_fused<<<nblkE + 1 + 72, 256>>>(dst, ew, Wx, Wh, bx, bh, bg, E, nblkE);
    // 2: single-pass scan + dinv (self-cleans g_pack for next replay)
    k_scan_fused<<<nblkS, SCAN_T>>>(n, E);
    // 3: atomic-free CSR scatter
    k_scatter<<<nblkE, 256>>>(src, dst, ew, E);
    // 4: agg1 -> A (2-edge float4 gather; tf32 GEMM layout output)
    k_agg1<<<nblkW, 256>>>(X, H, n);
    // 5: fused tc-GEMM + LSTM + tc head-GEMM (C prefetch + ILP LN reductions)
    const int FUSED_SMEM = SM_FLOATS * (int)sizeof(float);
    cudaFuncSetAttribute(k_gemm_lstm_tc, cudaFuncAttributeMaxDynamicSharedMemorySize,
                         FUSED_SMEM);
    k_gemm_lstm_tc<<<(n + 63) / 64, 256, FUSED_SMEM>>>(
        C, wc, lnhs, lnhb, lncs, lncb, lnos, lnob, skip, W1,
        outHidden, outCell, n);
    // 6: agg2 (2-edge float4 gather) + fc epilogue -> t
    k_agg2<<<nblkW, 256>>>(b1, W2, n);
    // 7: agg3 -> out
    k_agg3<<<nblkN, 256>>>(X, b2, out, n);
}